// round 3
// baseline (speedup 1.0000x reference)
#include <cuda_runtime.h>

// Problem constants (fixed shapes)
#define NN 50000
#define EE 800000
#define DD 256
#define KK 256
#define NCLS 40
#define STATS_BLOCKS 200
#define BN_EPS 1e-5f

// ---------------- scratch (static device globals; no allocation) ----------------
__device__ float g_G[NN * 512];        // GEMM output [N, 2*D] (self | neigh)
__device__ float g_Z[NN * DD];         // pre-BN activations
__device__ float g_H[NN * DD];         // post-BN/ReLU activations
__device__ float g_part[STATS_BLOCKS * 512];  // per-block column sums / sumsq
__device__ float g_affine[1024];       // [0:256)=A_z, [256:512)=B_z, [512:768)=A_plm, [768:1024)=B_plm
__device__ float g_invdeg[NN];
__device__ int   g_deg[NN];
__device__ int   g_fill[NN];
__device__ int   g_rowptr[NN + 1];
__device__ int   g_csr[EE];

// ---------------- CSR build ----------------
__global__ void k_hist(const int* __restrict__ dst) {
    int e = blockIdx.x * blockDim.x + threadIdx.x;
    if (e < EE) atomicAdd(&g_deg[dst[e]], 1);
}

// single-block exclusive scan of g_deg -> g_rowptr (n = NN)
__global__ void k_scan() {
    const int n = NN;
    const int CH = (n + 1023) / 1024;  // 49
    __shared__ int wsum[32];
    int t = threadIdx.x, lane = t & 31, w = t >> 5;
    int c0 = t * CH;
    int local = 0;
    for (int i = 0; i < CH; i++) {
        int idx = c0 + i;
        if (idx < n) local += g_deg[idx];
    }
    int v = local;
#pragma unroll
    for (int o = 1; o < 32; o <<= 1) {
        int u = __shfl_up_sync(0xffffffffu, v, o);
        if (lane >= o) v += u;
    }
    if (lane == 31) wsum[w] = v;
    __syncthreads();
    if (w == 0) {
        int x = wsum[lane];
#pragma unroll
        for (int o = 1; o < 32; o <<= 1) {
            int u = __shfl_up_sync(0xffffffffu, x, o);
            if (lane >= o) x += u;
        }
        wsum[lane] = x;
    }
    __syncthreads();
    int excl = (v - local) + (w > 0 ? wsum[w - 1] : 0);
    int run = excl;
    for (int i = 0; i < CH; i++) {
        int idx = c0 + i;
        if (idx < n) {
            g_rowptr[idx] = run;
            run += g_deg[idx];
        }
    }
    if (t == 1023) g_rowptr[n] = wsum[31];
}

__global__ void k_invdeg() {
    int i = blockIdx.x * blockDim.x + threadIdx.x;
    if (i < NN) g_invdeg[i] = 1.0f / fmaxf((float)g_deg[i], 1.0f);
}

__global__ void k_scatter(const int* __restrict__ src, const int* __restrict__ dst) {
    int e = blockIdx.x * blockDim.x + threadIdx.x;
    if (e < EE) {
        int d = dst[e];
        int pos = g_rowptr[d] + atomicAdd(&g_fill[d], 1);
        g_csr[pos] = src[e];
    }
}

// ---------------- GEMM: C[N, Mtot] = A[N,256] @ [Bself; Bneigh]^T ----------------
// Bself rows [0, Ms), Bneigh rows [Ms, Mtot). All K-major (row-major, K=256 inner).
__global__ void __launch_bounds__(256) k_gemm(
    const float* __restrict__ A, int N,
    const float* __restrict__ Bself, int Ms,
    const float* __restrict__ Bneigh, int Mtot,
    float* __restrict__ C) {
    __shared__ __align__(16) float As[16][132];
    __shared__ __align__(16) float Bs[16][132];
    const int bm = blockIdx.y * 128;
    const int bn = blockIdx.x * 128;
    const int tid = threadIdx.x;
    const int tr = (tid >> 4) << 3;  // 0..120
    const int tc = (tid & 15) << 3;  // 0..120

    float acc[8][8];
#pragma unroll
    for (int i = 0; i < 8; i++)
#pragma unroll
        for (int j = 0; j < 8; j++) acc[i][j] = 0.0f;

    for (int k0 = 0; k0 < KK; k0 += 16) {
#pragma unroll
        for (int i = 0; i < 2; i++) {
            int l = tid + i * 256;          // 0..511
            int r = l >> 2;                 // 0..127
            int cg = (l & 3) << 2;          // 0,4,8,12
            int ar = bm + r;
            float4 av = make_float4(0.f, 0.f, 0.f, 0.f);
            if (ar < N) av = *reinterpret_cast<const float4*>(A + ar * KK + k0 + cg);
            As[cg + 0][r] = av.x; As[cg + 1][r] = av.y;
            As[cg + 2][r] = av.z; As[cg + 3][r] = av.w;

            int br = bn + r;
            float4 bv = make_float4(0.f, 0.f, 0.f, 0.f);
            if (br < Mtot) {
                const float* bp = (br < Ms) ? (Bself + br * KK) : (Bneigh + (br - Ms) * KK);
                bv = *reinterpret_cast<const float4*>(bp + k0 + cg);
            }
            Bs[cg + 0][r] = bv.x; Bs[cg + 1][r] = bv.y;
            Bs[cg + 2][r] = bv.z; Bs[cg + 3][r] = bv.w;
        }
        __syncthreads();
#pragma unroll
        for (int k = 0; k < 16; k++) {
            float4 a0 = *reinterpret_cast<const float4*>(&As[k][tr]);
            float4 a1 = *reinterpret_cast<const float4*>(&As[k][tr + 4]);
            float4 b0 = *reinterpret_cast<const float4*>(&Bs[k][tc]);
            float4 b1 = *reinterpret_cast<const float4*>(&Bs[k][tc + 4]);
            float av[8] = {a0.x, a0.y, a0.z, a0.w, a1.x, a1.y, a1.z, a1.w};
            float bv[8] = {b0.x, b0.y, b0.z, b0.w, b1.x, b1.y, b1.z, b1.w};
#pragma unroll
            for (int i = 0; i < 8; i++)
#pragma unroll
                for (int j = 0; j < 8; j++)
                    acc[i][j] = fmaf(av[i], bv[j], acc[i][j]);
        }
        __syncthreads();
    }

#pragma unroll
    for (int i = 0; i < 8; i++) {
        int r = bm + tr + i;
        if (r < N) {
#pragma unroll
            for (int j = 0; j < 8; j += 4) {
                int col = bn + tc + j;
                if (col + 4 <= Mtot) {
                    float4 v = make_float4(acc[i][j], acc[i][j + 1], acc[i][j + 2], acc[i][j + 3]);
                    *reinterpret_cast<float4*>(C + r * Mtot + col) = v;
                }
            }
        }
    }
}

// ---------------- Aggregation: Z[i,c] = G[i,c] + invdeg[i]*sum_e G[csr[e], D+c] + bias[c] ----------------
// One block per node; thread c handles column c. M = 2*D row stride of G.
__global__ void k_agg(const float* __restrict__ G, int M, int D,
                      const float* __restrict__ bias, float* __restrict__ Z) {
    int i = blockIdx.x;
    int c = threadIdx.x;
    if (c >= D) return;
    int e0 = g_rowptr[i];
    int e1 = g_rowptr[i + 1];
    const float* Gn = G + D;  // neigh half
    float accn = 0.0f;
    int e = e0;
    for (; e + 4 <= e1; e += 4) {
        int s0 = g_csr[e + 0];
        int s1 = g_csr[e + 1];
        int s2 = g_csr[e + 2];
        int s3 = g_csr[e + 3];
        float v0 = Gn[s0 * M + c];
        float v1 = Gn[s1 * M + c];
        float v2 = Gn[s2 * M + c];
        float v3 = Gn[s3 * M + c];
        accn += (v0 + v1) + (v2 + v3);
    }
    for (; e < e1; e++) accn += Gn[g_csr[e] * M + c];
    float self = G[i * M + c];
    Z[i * D + c] = fmaf(g_invdeg[i], accn, self) + bias[c];
}

// ---------------- column stats (deterministic 2-stage) ----------------
__global__ void k_colstats(const float* __restrict__ X) {
    int c = threadIdx.x;  // 256
    int rows_per = (NN + gridDim.x - 1) / gridDim.x;
    int r0 = blockIdx.x * rows_per;
    int r1 = min(NN, r0 + rows_per);
    float s = 0.f, s2 = 0.f;
#pragma unroll 4
    for (int r = r0; r < r1; r++) {
        float v = X[r * DD + c];
        s += v;
        s2 = fmaf(v, v, s2);
    }
    g_part[blockIdx.x * 512 + c] = s;
    g_part[blockIdx.x * 512 + 256 + c] = s2;
}

// AB[c] = gamma*rsqrt(var+eps), AB[256+c] = beta - mean*AB[c]
__global__ void k_affine(const float* __restrict__ gamma, const float* __restrict__ beta,
                         float* __restrict__ AB) {
    int c = threadIdx.x;  // 256
    float s = 0.f, s2 = 0.f;
    for (int b = 0; b < STATS_BLOCKS; b++) {
        s += g_part[b * 512 + c];
        s2 += g_part[b * 512 + 256 + c];
    }
    float m = s / (float)NN;
    float var = s2 / (float)NN - m * m;
    float a = gamma[c] * rsqrtf(var + BN_EPS);
    AB[c] = a;
    AB[256 + c] = beta[c] - m * a;
}

// ---------------- fused BN (+residual BN) + ReLU ----------------
// layer0: H = relu(Az*Z + Bz + Ap*P + Bp)
__global__ void k_bn0(const float* __restrict__ Z, const float* __restrict__ P,
                      float* __restrict__ H) {
    int q = blockIdx.x * blockDim.x + threadIdx.x;  // float4 id, exact grid
    int cb = (q & 63) << 2;
    float4 z = reinterpret_cast<const float4*>(Z)[q];
    float4 p = reinterpret_cast<const float4*>(P)[q];
    float4 r;
    r.x = fmaf(g_affine[cb + 0], z.x, g_affine[256 + cb + 0]) + fmaf(g_affine[512 + cb + 0], p.x, g_affine[768 + cb + 0]);
    r.y = fmaf(g_affine[cb + 1], z.y, g_affine[256 + cb + 1]) + fmaf(g_affine[512 + cb + 1], p.y, g_affine[768 + cb + 1]);
    r.z = fmaf(g_affine[cb + 2], z.z, g_affine[256 + cb + 2]) + fmaf(g_affine[512 + cb + 2], p.z, g_affine[768 + cb + 2]);
    r.w = fmaf(g_affine[cb + 3], z.w, g_affine[256 + cb + 3]) + fmaf(g_affine[512 + cb + 3], p.w, g_affine[768 + cb + 3]);
    r.x = fmaxf(r.x, 0.f); r.y = fmaxf(r.y, 0.f); r.z = fmaxf(r.z, 0.f); r.w = fmaxf(r.w, 0.f);
    reinterpret_cast<float4*>(H)[q] = r;
}

// layer1: H = relu(Az*Z + Bz)
__global__ void k_bn1(const float* __restrict__ Z, float* __restrict__ H) {
    int q = blockIdx.x * blockDim.x + threadIdx.x;
    int cb = (q & 63) << 2;
    float4 z = reinterpret_cast<const float4*>(Z)[q];
    float4 r;
    r.x = fmaf(g_affine[cb + 0], z.x, g_affine[256 + cb + 0]);
    r.y = fmaf(g_affine[cb + 1], z.y, g_affine[256 + cb + 1]);
    r.z = fmaf(g_affine[cb + 2], z.z, g_affine[256 + cb + 2]);
    r.w = fmaf(g_affine[cb + 3], z.w, g_affine[256 + cb + 3]);
    r.x = fmaxf(r.x, 0.f); r.y = fmaxf(r.y, 0.f); r.z = fmaxf(r.z, 0.f); r.w = fmaxf(r.w, 0.f);
    reinterpret_cast<float4*>(H)[q] = r;
}

// ---------------- launch ----------------
extern "C" void kernel_launch(void* const* d_in, const int* in_sizes, int n_in,
                              void* d_out, int out_size) {
    const float* LLM = (const float*)d_in[0];
    const float* PLM = (const float*)d_in[1];
    const int* src   = (const int*)d_in[2];
    const int* dst   = (const int*)d_in[3];
    const float* ws0 = (const float*)d_in[4];
    const float* wn0 = (const float*)d_in[5];
    const float* b0  = (const float*)d_in[6];
    const float* ws1 = (const float*)d_in[7];
    const float* wn1 = (const float*)d_in[8];
    const float* b1  = (const float*)d_in[9];
    const float* ws2 = (const float*)d_in[10];
    const float* wn2 = (const float*)d_in[11];
    const float* b2  = (const float*)d_in[12];
    const float* bn0w = (const float*)d_in[13];
    const float* bn0b = (const float*)d_in[14];
    const float* bn1w = (const float*)d_in[15];
    const float* bn1b = (const float*)d_in[16];
    float* out = (float*)d_out;

    float *pG, *pZ, *pH, *pAff;
    int *pDeg, *pFill;
    cudaGetSymbolAddress((void**)&pG, g_G);
    cudaGetSymbolAddress((void**)&pZ, g_Z);
    cudaGetSymbolAddress((void**)&pH, g_H);
    cudaGetSymbolAddress((void**)&pAff, g_affine);
    cudaGetSymbolAddress((void**)&pDeg, g_deg);
    cudaGetSymbolAddress((void**)&pFill, g_fill);

    // --- CSR build ---
    cudaMemsetAsync(pDeg, 0, NN * sizeof(int), 0);
    cudaMemsetAsync(pFill, 0, NN * sizeof(int), 0);
    k_hist<<<(EE + 255) / 256, 256>>>(dst);
    k_scan<<<1, 1024>>>();
    k_invdeg<<<(NN + 255) / 256, 256>>>();
    k_scatter<<<(EE + 255) / 256, 256>>>(src, dst);

    const int elem_blocks = (NN * DD / 4) / 256;  // 12500, exact
    dim3 ggemm(4, (NN + 127) / 128);              // Mtot = 512
    dim3 ggemm2(1, (NN + 127) / 128);             // Mtot = 80

    // --- PLM BN stats (same bn0 weights) ---
    k_colstats<<<STATS_BLOCKS, 256>>>(PLM);
    k_affine<<<1, 256>>>(bn0w, bn0b, pAff + 512);

    // --- layer 0 ---
    k_gemm<<<ggemm, 256>>>(LLM, NN, ws0, 256, wn0, 512, pG);
    k_agg<<<NN, 256>>>(pG, 512, 256, b0, pZ);
    k_colstats<<<STATS_BLOCKS, 256>>>(pZ);
    k_affine<<<1, 256>>>(bn0w, bn0b, pAff);
    k_bn0<<<elem_blocks, 256>>>(pZ, PLM, pH);

    // --- layer 1 ---
    k_gemm<<<ggemm, 256>>>(pH, NN, ws1, 256, wn1, 512, pG);
    k_agg<<<NN, 256>>>(pG, 512, 256, b1, pZ);
    k_colstats<<<STATS_BLOCKS, 256>>>(pZ);
    k_affine<<<1, 256>>>(bn1w, bn1b, pAff);
    k_bn1<<<elem_blocks, 256>>>(pZ, pH);

    // --- layer 2 (output) ---
    k_gemm<<<ggemm2, 256>>>(pH, NN, ws2, NCLS, wn2, 2 * NCLS, pG);
    k_agg<<<NN, 64>>>(pG, 2 * NCLS, NCLS, b2, out);

    (void)in_sizes; (void)n_in; (void)out_size;
}

// round 4
// speedup vs baseline: 1.0777x; 1.0777x over previous
#include <cuda_runtime.h>
#include <cstdint>

// Problem constants (fixed shapes)
#define NN 50000
#define EE 800000
#define DD 256
#define KK 256
#define NCLS 40
#define STATS_BLOCKS 200
#define BN_EPS 1e-5f

// ---------------- scratch (static device globals; no allocation) ----------------
__device__ float g_G[NN * 512];        // GEMM output [N, 2*D] (self | neigh)
__device__ float g_Z[NN * DD];         // pre-BN activations
__device__ float g_H[NN * DD];         // post-BN/ReLU activations
__device__ float g_part[STATS_BLOCKS * 512];  // per-block column sums / sumsq
__device__ float g_affine[1024];       // [0:256)=A_z, [256:512)=B_z, [512:768)=A_plm, [768:1024)=B_plm
__device__ float g_invdeg[NN];
__device__ int   g_deg[NN];
__device__ int   g_fill[NN];
__device__ int   g_rowptr[NN + 1];
__device__ int   g_csr[EE];

// ---------------- CSR build ----------------
__global__ void k_hist(const int* __restrict__ dst) {
    int e = blockIdx.x * blockDim.x + threadIdx.x;
    if (e < EE) atomicAdd(&g_deg[dst[e]], 1);
}

// single-block exclusive scan of g_deg -> g_rowptr (n = NN)
__global__ void k_scan() {
    const int n = NN;
    const int CH = (n + 1023) / 1024;  // 49
    __shared__ int wsum[32];
    int t = threadIdx.x, lane = t & 31, w = t >> 5;
    int c0 = t * CH;
    int local = 0;
    for (int i = 0; i < CH; i++) {
        int idx = c0 + i;
        if (idx < n) local += g_deg[idx];
    }
    int v = local;
#pragma unroll
    for (int o = 1; o < 32; o <<= 1) {
        int u = __shfl_up_sync(0xffffffffu, v, o);
        if (lane >= o) v += u;
    }
    if (lane == 31) wsum[w] = v;
    __syncthreads();
    if (w == 0) {
        int x = wsum[lane];
#pragma unroll
        for (int o = 1; o < 32; o <<= 1) {
            int u = __shfl_up_sync(0xffffffffu, x, o);
            if (lane >= o) x += u;
        }
        wsum[lane] = x;
    }
    __syncthreads();
    int excl = (v - local) + (w > 0 ? wsum[w - 1] : 0);
    int run = excl;
    for (int i = 0; i < CH; i++) {
        int idx = c0 + i;
        if (idx < n) {
            g_rowptr[idx] = run;
            run += g_deg[idx];
        }
    }
    if (t == 1023) g_rowptr[n] = wsum[31];
}

__global__ void k_invdeg() {
    int i = blockIdx.x * blockDim.x + threadIdx.x;
    if (i < NN) g_invdeg[i] = 1.0f / fmaxf((float)g_deg[i], 1.0f);
}

__global__ void k_scatter(const int* __restrict__ src, const int* __restrict__ dst) {
    int e = blockIdx.x * blockDim.x + threadIdx.x;
    if (e < EE) {
        int d = dst[e];
        int pos = g_rowptr[d] + atomicAdd(&g_fill[d], 1);
        g_csr[pos] = src[e];
    }
}

// ================= TF32 tensor-core GEMM (3xTF32 split) =================
// C[N, 512] = A[N, 256] @ [Bself(256 rows); Bneigh(256 rows)]^T
// Block tile 128x128, BK=16, 8 warps, warp tile 64x32 via mma.m16n8k8.tf32.

__device__ __forceinline__ void f2tf32_split(float v, uint32_t& hi, uint32_t& lo) {
    uint32_t h;
    asm("cvt.rna.tf32.f32 %0, %1;" : "=r"(h) : "f"(v));
    float r = v - __uint_as_float(h);
    uint32_t l;
    asm("cvt.rna.tf32.f32 %0, %1;" : "=r"(l) : "f"(r));
    hi = h; lo = l;
}

__device__ __forceinline__ void mma_tf32(float* d, const uint32_t* a, const uint32_t* b) {
    asm volatile(
        "mma.sync.aligned.m16n8k8.row.col.f32.tf32.tf32.f32 "
        "{%0,%1,%2,%3}, {%4,%5,%6,%7}, {%8,%9}, {%0,%1,%2,%3};"
        : "+f"(d[0]), "+f"(d[1]), "+f"(d[2]), "+f"(d[3])
        : "r"(a[0]), "r"(a[1]), "r"(a[2]), "r"(a[3]), "r"(b[0]), "r"(b[1]));
}

#define TPAD 20  // smem k-stride (16 + 4) -> conflict-free stores AND frag loads

__global__ void __launch_bounds__(256) k_gemm_tf32(
    const float* __restrict__ A, int N,
    const float* __restrict__ Bself,
    const float* __restrict__ Bneigh,
    float* __restrict__ C) {
    __shared__ __align__(16) float As_hi[128][TPAD];
    __shared__ __align__(16) float As_lo[128][TPAD];
    __shared__ __align__(16) float Bs_hi[128][TPAD];
    __shared__ __align__(16) float Bs_lo[128][TPAD];

    const int tid = threadIdx.x;
    const int lane = tid & 31;
    const int wid = tid >> 5;
    const int wm = (wid >> 2) * 64;  // 0 or 64
    const int wn = (wid & 3) * 32;   // 0..96
    const int g = lane >> 2;         // 0..7
    const int t = lane & 3;          // 0..3
    const int bm = blockIdx.y * 128;
    const int bn = blockIdx.x * 128;

    // loader coordinates: 2 float4 per thread per tile (128 rows x 16 cols)
    const int lr0 = tid >> 2;                 // rows for f-index tid
    const int lr1 = (tid + 256) >> 2;         // rows for f-index tid+256
    const int lc0 = (tid & 3) * 4;            // col group (same for both)
    const bool aok0 = (bm + lr0) < N;
    const bool aok1 = (bm + lr1) < N;
    // B rows always valid (Mtot = 512 exact)
    const float* bp0 = (bn + lr0) < 256 ? (Bself + (bn + lr0) * KK) : (Bneigh + (bn + lr0 - 256) * KK);
    const float* bp1 = (bn + lr1) < 256 ? (Bself + (bn + lr1) * KK) : (Bneigh + (bn + lr1 - 256) * KK);

    float acc[4][4][4];
#pragma unroll
    for (int i = 0; i < 4; i++)
#pragma unroll
        for (int j = 0; j < 4; j++)
#pragma unroll
            for (int r = 0; r < 4; r++) acc[i][j][r] = 0.0f;

    float4 pa0, pa1, pb0, pb1;
    const float4 z4 = make_float4(0.f, 0.f, 0.f, 0.f);

    // prefetch chunk 0
    {
        pa0 = aok0 ? *reinterpret_cast<const float4*>(A + (bm + lr0) * KK + lc0) : z4;
        pa1 = aok1 ? *reinterpret_cast<const float4*>(A + (bm + lr1) * KK + lc0) : z4;
        pb0 = *reinterpret_cast<const float4*>(bp0 + lc0);
        pb1 = *reinterpret_cast<const float4*>(bp1 + lc0);
    }

    for (int kc = 0; kc < KK / 16; kc++) {
        // convert + store current chunk to smem
        {
            float4 h, l;
            f2tf32_split(pa0.x, *(uint32_t*)&h.x, *(uint32_t*)&l.x);
            f2tf32_split(pa0.y, *(uint32_t*)&h.y, *(uint32_t*)&l.y);
            f2tf32_split(pa0.z, *(uint32_t*)&h.z, *(uint32_t*)&l.z);
            f2tf32_split(pa0.w, *(uint32_t*)&h.w, *(uint32_t*)&l.w);
            *reinterpret_cast<float4*>(&As_hi[lr0][lc0]) = h;
            *reinterpret_cast<float4*>(&As_lo[lr0][lc0]) = l;
            f2tf32_split(pa1.x, *(uint32_t*)&h.x, *(uint32_t*)&l.x);
            f2tf32_split(pa1.y, *(uint32_t*)&h.y, *(uint32_t*)&l.y);
            f2tf32_split(pa1.z, *(uint32_t*)&h.z, *(uint32_t*)&l.z);
            f2tf32_split(pa1.w, *(uint32_t*)&h.w, *(uint32_t*)&l.w);
            *reinterpret_cast<float4*>(&As_hi[lr1][lc0]) = h;
            *reinterpret_cast<float4*>(&As_lo[lr1][lc0]) = l;
            f2tf32_split(pb0.x, *(uint32_t*)&h.x, *(uint32_t*)&l.x);
            f2tf32_split(pb0.y, *(uint32_t*)&h.y, *(uint32_t*)&l.y);
            f2tf32_split(pb0.z, *(uint32_t*)&h.z, *(uint32_t*)&l.z);
            f2tf32_split(pb0.w, *(uint32_t*)&h.w, *(uint32_t*)&l.w);
            *reinterpret_cast<float4*>(&Bs_hi[lr0][lc0]) = h;
            *reinterpret_cast<float4*>(&Bs_lo[lr0][lc0]) = l;
            f2tf32_split(pb1.x, *(uint32_t*)&h.x, *(uint32_t*)&l.x);
            f2tf32_split(pb1.y, *(uint32_t*)&h.y, *(uint32_t*)&l.y);
            f2tf32_split(pb1.z, *(uint32_t*)&h.z, *(uint32_t*)&l.z);
            f2tf32_split(pb1.w, *(uint32_t*)&h.w, *(uint32_t*)&l.w);
            *reinterpret_cast<float4*>(&Bs_hi[lr1][lc0]) = h;
            *reinterpret_cast<float4*>(&Bs_lo[lr1][lc0]) = l;
        }
        __syncthreads();

        // prefetch next chunk (overlaps with MMA below)
        if (kc + 1 < KK / 16) {
            int k0 = (kc + 1) * 16;
            pa0 = aok0 ? *reinterpret_cast<const float4*>(A + (bm + lr0) * KK + k0 + lc0) : z4;
            pa1 = aok1 ? *reinterpret_cast<const float4*>(A + (bm + lr1) * KK + k0 + lc0) : z4;
            pb0 = *reinterpret_cast<const float4*>(bp0 + k0 + lc0);
            pb1 = *reinterpret_cast<const float4*>(bp1 + k0 + lc0);
        }

#pragma unroll
        for (int ks = 0; ks < 2; ks++) {
            const int k0 = ks * 8;
            uint32_t ah[4][4], al[4][4], bh[4][2], bl[4][2];
#pragma unroll
            for (int mt = 0; mt < 4; mt++) {
                int m0 = wm + mt * 16;
                ah[mt][0] = __float_as_uint(As_hi[m0 + g][k0 + t]);
                ah[mt][1] = __float_as_uint(As_hi[m0 + g + 8][k0 + t]);
                ah[mt][2] = __float_as_uint(As_hi[m0 + g][k0 + t + 4]);
                ah[mt][3] = __float_as_uint(As_hi[m0 + g + 8][k0 + t + 4]);
                al[mt][0] = __float_as_uint(As_lo[m0 + g][k0 + t]);
                al[mt][1] = __float_as_uint(As_lo[m0 + g + 8][k0 + t]);
                al[mt][2] = __float_as_uint(As_lo[m0 + g][k0 + t + 4]);
                al[mt][3] = __float_as_uint(As_lo[m0 + g + 8][k0 + t + 4]);
            }
#pragma unroll
            for (int nt = 0; nt < 4; nt++) {
                int n0 = wn + nt * 8;
                bh[nt][0] = __float_as_uint(Bs_hi[n0 + g][k0 + t]);
                bh[nt][1] = __float_as_uint(Bs_hi[n0 + g][k0 + t + 4]);
                bl[nt][0] = __float_as_uint(Bs_lo[n0 + g][k0 + t]);
                bl[nt][1] = __float_as_uint(Bs_lo[n0 + g][k0 + t + 4]);
            }
#pragma unroll
            for (int mt = 0; mt < 4; mt++)
#pragma unroll
                for (int nt = 0; nt < 4; nt++) {
                    mma_tf32(acc[mt][nt], ah[mt], bh[nt]);   // hi*hi
                    mma_tf32(acc[mt][nt], ah[mt], bl[nt]);   // hi*lo
                    mma_tf32(acc[mt][nt], al[mt], bh[nt]);   // lo*hi
                }
        }
        __syncthreads();
    }

    // epilogue: c0 (g, 2t), c1 (g, 2t+1), c2 (g+8, 2t), c3 (g+8, 2t+1)
#pragma unroll
    for (int mt = 0; mt < 4; mt++) {
#pragma unroll
        for (int nt = 0; nt < 4; nt++) {
            int row = bm + wm + mt * 16 + g;
            int col = bn + wn + nt * 8 + 2 * t;
            if (row < N)
                *reinterpret_cast<float2*>(C + row * 512 + col) =
                    make_float2(acc[mt][nt][0], acc[mt][nt][1]);
            if (row + 8 < N)
                *reinterpret_cast<float2*>(C + (row + 8) * 512 + col) =
                    make_float2(acc[mt][nt][2], acc[mt][nt][3]);
        }
    }
}

// ---------------- SIMT GEMM (kept for small layer-2) ----------------
__global__ void __launch_bounds__(256) k_gemm(
    const float* __restrict__ A, int N,
    const float* __restrict__ Bself, int Ms,
    const float* __restrict__ Bneigh, int Mtot,
    float* __restrict__ C) {
    __shared__ __align__(16) float As[16][132];
    __shared__ __align__(16) float Bs[16][132];
    const int bm = blockIdx.y * 128;
    const int bn = blockIdx.x * 128;
    const int tid = threadIdx.x;
    const int tr = (tid >> 4) << 3;
    const int tc = (tid & 15) << 3;

    float acc[8][8];
#pragma unroll
    for (int i = 0; i < 8; i++)
#pragma unroll
        for (int j = 0; j < 8; j++) acc[i][j] = 0.0f;

    for (int k0 = 0; k0 < KK; k0 += 16) {
#pragma unroll
        for (int i = 0; i < 2; i++) {
            int l = tid + i * 256;
            int r = l >> 2;
            int cg = (l & 3) << 2;
            int ar = bm + r;
            float4 av = make_float4(0.f, 0.f, 0.f, 0.f);
            if (ar < N) av = *reinterpret_cast<const float4*>(A + ar * KK + k0 + cg);
            As[cg + 0][r] = av.x; As[cg + 1][r] = av.y;
            As[cg + 2][r] = av.z; As[cg + 3][r] = av.w;

            int br = bn + r;
            float4 bv = make_float4(0.f, 0.f, 0.f, 0.f);
            if (br < Mtot) {
                const float* bp = (br < Ms) ? (Bself + br * KK) : (Bneigh + (br - Ms) * KK);
                bv = *reinterpret_cast<const float4*>(bp + k0 + cg);
            }
            Bs[cg + 0][r] = bv.x; Bs[cg + 1][r] = bv.y;
            Bs[cg + 2][r] = bv.z; Bs[cg + 3][r] = bv.w;
        }
        __syncthreads();
#pragma unroll
        for (int k = 0; k < 16; k++) {
            float4 a0 = *reinterpret_cast<const float4*>(&As[k][tr]);
            float4 a1 = *reinterpret_cast<const float4*>(&As[k][tr + 4]);
            float4 b0 = *reinterpret_cast<const float4*>(&Bs[k][tc]);
            float4 b1 = *reinterpret_cast<const float4*>(&Bs[k][tc + 4]);
            float av[8] = {a0.x, a0.y, a0.z, a0.w, a1.x, a1.y, a1.z, a1.w};
            float bv[8] = {b0.x, b0.y, b0.z, b0.w, b1.x, b1.y, b1.z, b1.w};
#pragma unroll
            for (int i = 0; i < 8; i++)
#pragma unroll
                for (int j = 0; j < 8; j++)
                    acc[i][j] = fmaf(av[i], bv[j], acc[i][j]);
        }
        __syncthreads();
    }

#pragma unroll
    for (int i = 0; i < 8; i++) {
        int r = bm + tr + i;
        if (r < N) {
#pragma unroll
            for (int j = 0; j < 8; j += 4) {
                int col = bn + tc + j;
                if (col + 4 <= Mtot) {
                    float4 v = make_float4(acc[i][j], acc[i][j + 1], acc[i][j + 2], acc[i][j + 3]);
                    *reinterpret_cast<float4*>(C + r * Mtot + col) = v;
                }
            }
        }
    }
}

// ---------------- Aggregation ----------------
__global__ void k_agg(const float* __restrict__ G, int M, int D,
                      const float* __restrict__ bias, float* __restrict__ Z) {
    int i = blockIdx.x;
    int c = threadIdx.x;
    if (c >= D) return;
    int e0 = g_rowptr[i];
    int e1 = g_rowptr[i + 1];
    const float* Gn = G + D;
    float accn = 0.0f;
    int e = e0;
    for (; e + 4 <= e1; e += 4) {
        int s0 = g_csr[e + 0];
        int s1 = g_csr[e + 1];
        int s2 = g_csr[e + 2];
        int s3 = g_csr[e + 3];
        float v0 = Gn[s0 * M + c];
        float v1 = Gn[s1 * M + c];
        float v2 = Gn[s2 * M + c];
        float v3 = Gn[s3 * M + c];
        accn += (v0 + v1) + (v2 + v3);
    }
    for (; e < e1; e++) accn += Gn[g_csr[e] * M + c];
    float self = G[i * M + c];
    Z[i * D + c] = fmaf(g_invdeg[i], accn, self) + bias[c];
}

// ---------------- column stats (deterministic 2-stage) ----------------
__global__ void k_colstats(const float* __restrict__ X) {
    int c = threadIdx.x;
    int rows_per = (NN + gridDim.x - 1) / gridDim.x;
    int r0 = blockIdx.x * rows_per;
    int r1 = min(NN, r0 + rows_per);
    float s = 0.f, s2 = 0.f;
#pragma unroll 4
    for (int r = r0; r < r1; r++) {
        float v = X[r * DD + c];
        s += v;
        s2 = fmaf(v, v, s2);
    }
    g_part[blockIdx.x * 512 + c] = s;
    g_part[blockIdx.x * 512 + 256 + c] = s2;
}

__global__ void k_affine(const float* __restrict__ gamma, const float* __restrict__ beta,
                         float* __restrict__ AB) {
    int c = threadIdx.x;
    float s = 0.f, s2 = 0.f;
    for (int b = 0; b < STATS_BLOCKS; b++) {
        s += g_part[b * 512 + c];
        s2 += g_part[b * 512 + 256 + c];
    }
    float m = s / (float)NN;
    float var = s2 / (float)NN - m * m;
    float a = gamma[c] * rsqrtf(var + BN_EPS);
    AB[c] = a;
    AB[256 + c] = beta[c] - m * a;
}

// ---------------- fused BN (+residual BN) + ReLU ----------------
__global__ void k_bn0(const float* __restrict__ Z, const float* __restrict__ P,
                      float* __restrict__ H) {
    int q = blockIdx.x * blockDim.x + threadIdx.x;
    int cb = (q & 63) << 2;
    float4 z = reinterpret_cast<const float4*>(Z)[q];
    float4 p = reinterpret_cast<const float4*>(P)[q];
    float4 r;
    r.x = fmaf(g_affine[cb + 0], z.x, g_affine[256 + cb + 0]) + fmaf(g_affine[512 + cb + 0], p.x, g_affine[768 + cb + 0]);
    r.y = fmaf(g_affine[cb + 1], z.y, g_affine[256 + cb + 1]) + fmaf(g_affine[512 + cb + 1], p.y, g_affine[768 + cb + 1]);
    r.z = fmaf(g_affine[cb + 2], z.z, g_affine[256 + cb + 2]) + fmaf(g_affine[512 + cb + 2], p.z, g_affine[768 + cb + 2]);
    r.w = fmaf(g_affine[cb + 3], z.w, g_affine[256 + cb + 3]) + fmaf(g_affine[512 + cb + 3], p.w, g_affine[768 + cb + 3]);
    r.x = fmaxf(r.x, 0.f); r.y = fmaxf(r.y, 0.f); r.z = fmaxf(r.z, 0.f); r.w = fmaxf(r.w, 0.f);
    reinterpret_cast<float4*>(H)[q] = r;
}

__global__ void k_bn1(const float* __restrict__ Z, float* __restrict__ H) {
    int q = blockIdx.x * blockDim.x + threadIdx.x;
    int cb = (q & 63) << 2;
    float4 z = reinterpret_cast<const float4*>(Z)[q];
    float4 r;
    r.x = fmaf(g_affine[cb + 0], z.x, g_affine[256 + cb + 0]);
    r.y = fmaf(g_affine[cb + 1], z.y, g_affine[256 + cb + 1]);
    r.z = fmaf(g_affine[cb + 2], z.z, g_affine[256 + cb + 2]);
    r.w = fmaf(g_affine[cb + 3], z.w, g_affine[256 + cb + 3]);
    r.x = fmaxf(r.x, 0.f); r.y = fmaxf(r.y, 0.f); r.z = fmaxf(r.z, 0.f); r.w = fmaxf(r.w, 0.f);
    reinterpret_cast<float4*>(H)[q] = r;
}

// ---------------- launch ----------------
extern "C" void kernel_launch(void* const* d_in, const int* in_sizes, int n_in,
                              void* d_out, int out_size) {
    const float* LLM = (const float*)d_in[0];
    const float* PLM = (const float*)d_in[1];
    const int* src   = (const int*)d_in[2];
    const int* dst   = (const int*)d_in[3];
    const float* ws0 = (const float*)d_in[4];
    const float* wn0 = (const float*)d_in[5];
    const float* b0  = (const float*)d_in[6];
    const float* ws1 = (const float*)d_in[7];
    const float* wn1 = (const float*)d_in[8];
    const float* b1  = (const float*)d_in[9];
    const float* ws2 = (const float*)d_in[10];
    const float* wn2 = (const float*)d_in[11];
    const float* b2  = (const float*)d_in[12];
    const float* bn0w = (const float*)d_in[13];
    const float* bn0b = (const float*)d_in[14];
    const float* bn1w = (const float*)d_in[15];
    const float* bn1b = (const float*)d_in[16];
    float* out = (float*)d_out;

    float *pG, *pZ, *pH, *pAff;
    int *pDeg, *pFill;
    cudaGetSymbolAddress((void**)&pG, g_G);
    cudaGetSymbolAddress((void**)&pZ, g_Z);
    cudaGetSymbolAddress((void**)&pH, g_H);
    cudaGetSymbolAddress((void**)&pAff, g_affine);
    cudaGetSymbolAddress((void**)&pDeg, g_deg);
    cudaGetSymbolAddress((void**)&pFill, g_fill);

    // --- CSR build ---
    cudaMemsetAsync(pDeg, 0, NN * sizeof(int), 0);
    cudaMemsetAsync(pFill, 0, NN * sizeof(int), 0);
    k_hist<<<(EE + 255) / 256, 256>>>(dst);
    k_scan<<<1, 1024>>>();
    k_invdeg<<<(NN + 255) / 256, 256>>>();
    k_scatter<<<(EE + 255) / 256, 256>>>(src, dst);

    const int elem_blocks = (NN * DD / 4) / 256;  // 12500, exact
    dim3 ggemm(4, (NN + 127) / 128);              // Mtot = 512, tensor-core path
    dim3 ggemm2(1, (NN + 127) / 128);             // Mtot = 80, SIMT path

    // --- PLM BN stats (same bn0 weights) ---
    k_colstats<<<STATS_BLOCKS, 256>>>(PLM);
    k_affine<<<1, 256>>>(bn0w, bn0b, pAff + 512);

    // --- layer 0 ---
    k_gemm_tf32<<<ggemm, 256>>>(LLM, NN, ws0, wn0, pG);
    k_agg<<<NN, 256>>>(pG, 512, 256, b0, pZ);
    k_colstats<<<STATS_BLOCKS, 256>>>(pZ);
    k_affine<<<1, 256>>>(bn0w, bn0b, pAff);
    k_bn0<<<elem_blocks, 256>>>(pZ, PLM, pH);

    // --- layer 1 ---
    k_gemm_tf32<<<ggemm, 256>>>(pH, NN, ws1, wn1, pG);
    k_agg<<<NN, 256>>>(pG, 512, 256, b1, pZ);
    k_colstats<<<STATS_BLOCKS, 256>>>(pZ);
    k_affine<<<1, 256>>>(bn1w, bn1b, pAff);
    k_bn1<<<elem_blocks, 256>>>(pZ, pH);

    // --- layer 2 (output) ---
    k_gemm<<<ggemm2, 256>>>(pH, NN, ws2, NCLS, wn2, 2 * NCLS, pG);
    k_agg<<<NN, 64>>>(pG, 2 * NCLS, NCLS, b2, out);

    (void)in_sizes; (void)n_in; (void)out_size;
}

// round 5
// speedup vs baseline: 1.2461x; 1.1562x over previous
#include <cuda_runtime.h>
#include <cstdint>

// Problem constants (fixed shapes)
#define NN 50000
#define EE 800000
#define DD 256
#define KK 256
#define NCLS 40
#define STATS_BLOCKS 400
#define BN_EPS 1e-5f

// ---------------- scratch (static device globals; no allocation) ----------------
__device__ __align__(16) float g_Gs[NN * DD];   // GEMM self output [N,256]
__device__ __align__(16) float g_Gn[NN * DD];   // GEMM neigh output [N,256] (dense gather target)
__device__ __align__(16) float g_Z[NN * DD];    // pre-BN activations
__device__ __align__(16) float g_H[NN * DD];    // post-BN/ReLU activations
__device__ float g_part[STATS_BLOCKS * 512];    // per-block column sums / sumsq
__device__ float g_affine[1024];                // [0:256)=A_z,[256:512)=B_z,[512:768)=A_plm,[768:1024)=B_plm
__device__ float g_invdeg[NN];
__device__ __align__(16) int g_deg[NN];
__device__ __align__(16) int g_fill[NN];
__device__ int g_rowptr[NN + 1];
__device__ int g_csr[EE];

// ---------------- zero deg/fill ----------------
__global__ void k_zero() {
    int q = blockIdx.x * blockDim.x + threadIdx.x;  // int4 index, NN/4 = 12500
    if (q < NN / 4) {
        int4 z = make_int4(0, 0, 0, 0);
        reinterpret_cast<int4*>(g_deg)[q] = z;
        reinterpret_cast<int4*>(g_fill)[q] = z;
    }
}

// ---------------- CSR build ----------------
__global__ void k_hist(const int* __restrict__ dst) {
    int e = blockIdx.x * blockDim.x + threadIdx.x;
    if (e < EE) atomicAdd(&g_deg[dst[e]], 1);
}

// single-block exclusive scan of g_deg -> g_rowptr; also writes invdeg
__global__ void k_scan() {
    const int n = NN;
    const int CH = (n + 1023) / 1024;  // 49
    __shared__ int wsum[32];
    int t = threadIdx.x, lane = t & 31, w = t >> 5;
    int c0 = t * CH;
    int local = 0;
    for (int i = 0; i < CH; i++) {
        int idx = c0 + i;
        if (idx < n) local += g_deg[idx];
    }
    int v = local;
#pragma unroll
    for (int o = 1; o < 32; o <<= 1) {
        int u = __shfl_up_sync(0xffffffffu, v, o);
        if (lane >= o) v += u;
    }
    if (lane == 31) wsum[w] = v;
    __syncthreads();
    if (w == 0) {
        int x = wsum[lane];
#pragma unroll
        for (int o = 1; o < 32; o <<= 1) {
            int u = __shfl_up_sync(0xffffffffu, x, o);
            if (lane >= o) x += u;
        }
        wsum[lane] = x;
    }
    __syncthreads();
    int excl = (v - local) + (w > 0 ? wsum[w - 1] : 0);
    int run = excl;
    for (int i = 0; i < CH; i++) {
        int idx = c0 + i;
        if (idx < n) {
            int d = g_deg[idx];
            g_rowptr[idx] = run;
            run += d;
            g_invdeg[idx] = 1.0f / fmaxf((float)d, 1.0f);
        }
    }
    if (t == 1023) g_rowptr[n] = wsum[31];
}

__global__ void k_scatter(const int* __restrict__ src, const int* __restrict__ dst) {
    int e = blockIdx.x * blockDim.x + threadIdx.x;
    if (e < EE) {
        int d = dst[e];
        int pos = g_rowptr[d] + atomicAdd(&g_fill[d], 1);
        g_csr[pos] = src[e];
    }
}

// ================= TF32 tensor-core GEMM (3xTF32 split) =================
__device__ __forceinline__ void f2tf32_split(float v, uint32_t& hi, uint32_t& lo) {
    uint32_t h;
    asm("cvt.rna.tf32.f32 %0, %1;" : "=r"(h) : "f"(v));
    float r = v - __uint_as_float(h);
    uint32_t l;
    asm("cvt.rna.tf32.f32 %0, %1;" : "=r"(l) : "f"(r));
    hi = h; lo = l;
}

__device__ __forceinline__ void mma_tf32(float* d, const uint32_t* a, const uint32_t* b) {
    asm volatile(
        "mma.sync.aligned.m16n8k8.row.col.f32.tf32.tf32.f32 "
        "{%0,%1,%2,%3}, {%4,%5,%6,%7}, {%8,%9}, {%0,%1,%2,%3};"
        : "+f"(d[0]), "+f"(d[1]), "+f"(d[2]), "+f"(d[3])
        : "r"(a[0]), "r"(a[1]), "r"(a[2]), "r"(a[3]), "r"(b[0]), "r"(b[1]));
}

#define TPAD 20

__global__ void __launch_bounds__(256) k_gemm_tf32(
    const float* __restrict__ A, int N,
    const float* __restrict__ Bself,
    const float* __restrict__ Bneigh,
    float* __restrict__ Cs, float* __restrict__ Cn) {
    __shared__ __align__(16) float As_hi[128][TPAD];
    __shared__ __align__(16) float As_lo[128][TPAD];
    __shared__ __align__(16) float Bs_hi[128][TPAD];
    __shared__ __align__(16) float Bs_lo[128][TPAD];

    const int tid = threadIdx.x;
    const int lane = tid & 31;
    const int wid = tid >> 5;
    const int wm = (wid >> 2) * 64;
    const int wn = (wid & 3) * 32;
    const int g = lane >> 2;
    const int t = lane & 3;
    const int bm = blockIdx.y * 128;
    const int bn = blockIdx.x * 128;

    const int lr0 = tid >> 2;
    const int lr1 = (tid + 256) >> 2;
    const int lc0 = (tid & 3) * 4;
    const bool aok0 = (bm + lr0) < N;
    const bool aok1 = (bm + lr1) < N;
    const float* bp0 = (bn + lr0) < 256 ? (Bself + (bn + lr0) * KK) : (Bneigh + (bn + lr0 - 256) * KK);
    const float* bp1 = (bn + lr1) < 256 ? (Bself + (bn + lr1) * KK) : (Bneigh + (bn + lr1 - 256) * KK);

    float acc[4][4][4];
#pragma unroll
    for (int i = 0; i < 4; i++)
#pragma unroll
        for (int j = 0; j < 4; j++)
#pragma unroll
            for (int r = 0; r < 4; r++) acc[i][j][r] = 0.0f;

    float4 pa0, pa1, pb0, pb1;
    const float4 z4 = make_float4(0.f, 0.f, 0.f, 0.f);

    pa0 = aok0 ? *reinterpret_cast<const float4*>(A + (bm + lr0) * KK + lc0) : z4;
    pa1 = aok1 ? *reinterpret_cast<const float4*>(A + (bm + lr1) * KK + lc0) : z4;
    pb0 = *reinterpret_cast<const float4*>(bp0 + lc0);
    pb1 = *reinterpret_cast<const float4*>(bp1 + lc0);

    for (int kc = 0; kc < KK / 16; kc++) {
        {
            float4 h, l;
            f2tf32_split(pa0.x, *(uint32_t*)&h.x, *(uint32_t*)&l.x);
            f2tf32_split(pa0.y, *(uint32_t*)&h.y, *(uint32_t*)&l.y);
            f2tf32_split(pa0.z, *(uint32_t*)&h.z, *(uint32_t*)&l.z);
            f2tf32_split(pa0.w, *(uint32_t*)&h.w, *(uint32_t*)&l.w);
            *reinterpret_cast<float4*>(&As_hi[lr0][lc0]) = h;
            *reinterpret_cast<float4*>(&As_lo[lr0][lc0]) = l;
            f2tf32_split(pa1.x, *(uint32_t*)&h.x, *(uint32_t*)&l.x);
            f2tf32_split(pa1.y, *(uint32_t*)&h.y, *(uint32_t*)&l.y);
            f2tf32_split(pa1.z, *(uint32_t*)&h.z, *(uint32_t*)&l.z);
            f2tf32_split(pa1.w, *(uint32_t*)&h.w, *(uint32_t*)&l.w);
            *reinterpret_cast<float4*>(&As_hi[lr1][lc0]) = h;
            *reinterpret_cast<float4*>(&As_lo[lr1][lc0]) = l;
            f2tf32_split(pb0.x, *(uint32_t*)&h.x, *(uint32_t*)&l.x);
            f2tf32_split(pb0.y, *(uint32_t*)&h.y, *(uint32_t*)&l.y);
            f2tf32_split(pb0.z, *(uint32_t*)&h.z, *(uint32_t*)&l.z);
            f2tf32_split(pb0.w, *(uint32_t*)&h.w, *(uint32_t*)&l.w);
            *reinterpret_cast<float4*>(&Bs_hi[lr0][lc0]) = h;
            *reinterpret_cast<float4*>(&Bs_lo[lr0][lc0]) = l;
            f2tf32_split(pb1.x, *(uint32_t*)&h.x, *(uint32_t*)&l.x);
            f2tf32_split(pb1.y, *(uint32_t*)&h.y, *(uint32_t*)&l.y);
            f2tf32_split(pb1.z, *(uint32_t*)&h.z, *(uint32_t*)&l.z);
            f2tf32_split(pb1.w, *(uint32_t*)&h.w, *(uint32_t*)&l.w);
            *reinterpret_cast<float4*>(&Bs_hi[lr1][lc0]) = h;
            *reinterpret_cast<float4*>(&Bs_lo[lr1][lc0]) = l;
        }
        __syncthreads();

        if (kc + 1 < KK / 16) {
            int k0 = (kc + 1) * 16;
            pa0 = aok0 ? *reinterpret_cast<const float4*>(A + (bm + lr0) * KK + k0 + lc0) : z4;
            pa1 = aok1 ? *reinterpret_cast<const float4*>(A + (bm + lr1) * KK + k0 + lc0) : z4;
            pb0 = *reinterpret_cast<const float4*>(bp0 + k0 + lc0);
            pb1 = *reinterpret_cast<const float4*>(bp1 + k0 + lc0);
        }

#pragma unroll
        for (int ks = 0; ks < 2; ks++) {
            const int k0 = ks * 8;
            uint32_t ah[4][4], al[4][4], bh[4][2], bl[4][2];
#pragma unroll
            for (int mt = 0; mt < 4; mt++) {
                int m0 = wm + mt * 16;
                ah[mt][0] = __float_as_uint(As_hi[m0 + g][k0 + t]);
                ah[mt][1] = __float_as_uint(As_hi[m0 + g + 8][k0 + t]);
                ah[mt][2] = __float_as_uint(As_hi[m0 + g][k0 + t + 4]);
                ah[mt][3] = __float_as_uint(As_hi[m0 + g + 8][k0 + t + 4]);
                al[mt][0] = __float_as_uint(As_lo[m0 + g][k0 + t]);
                al[mt][1] = __float_as_uint(As_lo[m0 + g + 8][k0 + t]);
                al[mt][2] = __float_as_uint(As_lo[m0 + g][k0 + t + 4]);
                al[mt][3] = __float_as_uint(As_lo[m0 + g + 8][k0 + t + 4]);
            }
#pragma unroll
            for (int nt = 0; nt < 4; nt++) {
                int n0 = wn + nt * 8;
                bh[nt][0] = __float_as_uint(Bs_hi[n0 + g][k0 + t]);
                bh[nt][1] = __float_as_uint(Bs_hi[n0 + g][k0 + t + 4]);
                bl[nt][0] = __float_as_uint(Bs_lo[n0 + g][k0 + t]);
                bl[nt][1] = __float_as_uint(Bs_lo[n0 + g][k0 + t + 4]);
            }
#pragma unroll
            for (int mt = 0; mt < 4; mt++)
#pragma unroll
                for (int nt = 0; nt < 4; nt++) {
                    mma_tf32(acc[mt][nt], ah[mt], bh[nt]);
                    mma_tf32(acc[mt][nt], ah[mt], bl[nt]);
                    mma_tf32(acc[mt][nt], al[mt], bh[nt]);
                }
        }
        __syncthreads();
    }

    float* Cbase = (bn < 256) ? (Cs + bn) : (Cn + (bn - 256));
#pragma unroll
    for (int mt = 0; mt < 4; mt++) {
#pragma unroll
        for (int nt = 0; nt < 4; nt++) {
            int row = bm + wm + mt * 16 + g;
            int col = wn + nt * 8 + 2 * t;
            if (row < N)
                *reinterpret_cast<float2*>(Cbase + row * 256 + col) =
                    make_float2(acc[mt][nt][0], acc[mt][nt][1]);
            if (row + 8 < N)
                *reinterpret_cast<float2*>(Cbase + (row + 8) * 256 + col) =
                    make_float2(acc[mt][nt][2], acc[mt][nt][3]);
        }
    }
}

// ---------------- SIMT GEMM for layer 2 (Mtot=80) ----------------
__global__ void __launch_bounds__(256) k_gemm_small(
    const float* __restrict__ A, int N,
    const float* __restrict__ Bself,
    const float* __restrict__ Bneigh,
    float* __restrict__ Cs, float* __restrict__ Cn) {
    __shared__ __align__(16) float As[16][132];
    __shared__ __align__(16) float Bs[16][132];
    const int Mtot = 2 * NCLS;  // 80
    const int bm = blockIdx.y * 128;
    const int tid = threadIdx.x;
    const int tr = (tid >> 4) << 3;
    const int tc = (tid & 15) << 3;

    float acc[8][8];
#pragma unroll
    for (int i = 0; i < 8; i++)
#pragma unroll
        for (int j = 0; j < 8; j++) acc[i][j] = 0.0f;

    for (int k0 = 0; k0 < KK; k0 += 16) {
#pragma unroll
        for (int i = 0; i < 2; i++) {
            int l = tid + i * 256;
            int r = l >> 2;
            int cg = (l & 3) << 2;
            int ar = bm + r;
            float4 av = make_float4(0.f, 0.f, 0.f, 0.f);
            if (ar < N) av = *reinterpret_cast<const float4*>(A + ar * KK + k0 + cg);
            As[cg + 0][r] = av.x; As[cg + 1][r] = av.y;
            As[cg + 2][r] = av.z; As[cg + 3][r] = av.w;

            float4 bv = make_float4(0.f, 0.f, 0.f, 0.f);
            if (r < Mtot) {
                const float* bp = (r < NCLS) ? (Bself + r * KK) : (Bneigh + (r - NCLS) * KK);
                bv = *reinterpret_cast<const float4*>(bp + k0 + cg);
            }
            Bs[cg + 0][r] = bv.x; Bs[cg + 1][r] = bv.y;
            Bs[cg + 2][r] = bv.z; Bs[cg + 3][r] = bv.w;
        }
        __syncthreads();
#pragma unroll
        for (int k = 0; k < 16; k++) {
            float4 a0 = *reinterpret_cast<const float4*>(&As[k][tr]);
            float4 a1 = *reinterpret_cast<const float4*>(&As[k][tr + 4]);
            float4 b0 = *reinterpret_cast<const float4*>(&Bs[k][tc]);
            float4 b1 = *reinterpret_cast<const float4*>(&Bs[k][tc + 4]);
            float av[8] = {a0.x, a0.y, a0.z, a0.w, a1.x, a1.y, a1.z, a1.w};
            float bv[8] = {b0.x, b0.y, b0.z, b0.w, b1.x, b1.y, b1.z, b1.w};
#pragma unroll
            for (int i = 0; i < 8; i++)
#pragma unroll
                for (int j = 0; j < 8; j++)
                    acc[i][j] = fmaf(av[i], bv[j], acc[i][j]);
        }
        __syncthreads();
    }

#pragma unroll
    for (int i = 0; i < 8; i++) {
        int r = bm + tr + i;
        if (r < N) {
#pragma unroll
            for (int j = 0; j < 8; j++) {
                int col = tc + j;
                if (col < NCLS) Cs[r * NCLS + col] = acc[i][j];
                else if (col < Mtot) Cn[r * NCLS + (col - NCLS)] = acc[i][j];
            }
        }
    }
}

// ---------------- Aggregation (float4, 4 nodes per block) ----------------
__global__ void __launch_bounds__(256) k_agg4(
    const float* __restrict__ Gs, const float* __restrict__ Gn,
    const float* __restrict__ bias, float* __restrict__ Z) {
    int sub = threadIdx.x >> 6;
    int cg = (threadIdx.x & 63) << 2;
    int i = blockIdx.x * 4 + sub;
    int e0 = g_rowptr[i];
    int e1 = g_rowptr[i + 1];
    float4 acc = make_float4(0.f, 0.f, 0.f, 0.f);
    int e = e0;
    for (; e + 4 <= e1; e += 4) {
        int s0 = g_csr[e + 0];
        int s1 = g_csr[e + 1];
        int s2 = g_csr[e + 2];
        int s3 = g_csr[e + 3];
        float4 v0 = __ldg(reinterpret_cast<const float4*>(Gn + s0 * DD + cg));
        float4 v1 = __ldg(reinterpret_cast<const float4*>(Gn + s1 * DD + cg));
        float4 v2 = __ldg(reinterpret_cast<const float4*>(Gn + s2 * DD + cg));
        float4 v3 = __ldg(reinterpret_cast<const float4*>(Gn + s3 * DD + cg));
        acc.x += (v0.x + v1.x) + (v2.x + v3.x);
        acc.y += (v0.y + v1.y) + (v2.y + v3.y);
        acc.z += (v0.z + v1.z) + (v2.z + v3.z);
        acc.w += (v0.w + v1.w) + (v2.w + v3.w);
    }
    for (; e < e1; e++) {
        float4 v = __ldg(reinterpret_cast<const float4*>(Gn + g_csr[e] * DD + cg));
        acc.x += v.x; acc.y += v.y; acc.z += v.z; acc.w += v.w;
    }
    float inv = g_invdeg[i];
    float4 self = *reinterpret_cast<const float4*>(Gs + i * DD + cg);
    float4 b = *reinterpret_cast<const float4*>(bias + cg);
    float4 r;
    r.x = fmaf(inv, acc.x, self.x) + b.x;
    r.y = fmaf(inv, acc.y, self.y) + b.y;
    r.z = fmaf(inv, acc.z, self.z) + b.z;
    r.w = fmaf(inv, acc.w, self.w) + b.w;
    *reinterpret_cast<float4*>(Z + i * DD + cg) = r;
}

// scalar agg for layer 2 (D = NCLS = 40)
__global__ void k_agg_small(const float* __restrict__ Gs, const float* __restrict__ Gn,
                            const float* __restrict__ bias, float* __restrict__ Z) {
    int i = blockIdx.x;
    int c = threadIdx.x;
    if (c >= NCLS) return;
    int e0 = g_rowptr[i];
    int e1 = g_rowptr[i + 1];
    float accn = 0.0f;
    int e = e0;
    for (; e + 4 <= e1; e += 4) {
        int s0 = g_csr[e + 0];
        int s1 = g_csr[e + 1];
        int s2 = g_csr[e + 2];
        int s3 = g_csr[e + 3];
        float v0 = __ldg(Gn + s0 * NCLS + c);
        float v1 = __ldg(Gn + s1 * NCLS + c);
        float v2 = __ldg(Gn + s2 * NCLS + c);
        float v3 = __ldg(Gn + s3 * NCLS + c);
        accn += (v0 + v1) + (v2 + v3);
    }
    for (; e < e1; e++) accn += __ldg(Gn + g_csr[e] * NCLS + c);
    Z[i * NCLS + c] = fmaf(g_invdeg[i], accn, Gs[i * NCLS + c]) + bias[c];
}

// ---------------- column stats (deterministic 2-stage) ----------------
__global__ void k_colstats(const float* __restrict__ X) {
    int c = threadIdx.x;
    int rows_per = (NN + gridDim.x - 1) / gridDim.x;
    int r0 = blockIdx.x * rows_per;
    int r1 = min(NN, r0 + rows_per);
    float s = 0.f, s2 = 0.f;
#pragma unroll 4
    for (int r = r0; r < r1; r++) {
        float v = X[r * DD + c];
        s += v;
        s2 = fmaf(v, v, s2);
    }
    g_part[blockIdx.x * 512 + c] = s;
    g_part[blockIdx.x * 512 + 256 + c] = s2;
}

__global__ void k_affine(const float* __restrict__ gamma, const float* __restrict__ beta,
                         float* __restrict__ AB) {
    int c = threadIdx.x;
    float s = 0.f, s2 = 0.f;
    for (int b = 0; b < STATS_BLOCKS; b++) {
        s += g_part[b * 512 + c];
        s2 += g_part[b * 512 + 256 + c];
    }
    float m = s / (float)NN;
    float var = s2 / (float)NN - m * m;
    float a = gamma[c] * rsqrtf(var + BN_EPS);
    AB[c] = a;
    AB[256 + c] = beta[c] - m * a;
}

// ---------------- fused BN (+residual BN) + ReLU ----------------
__global__ void k_bn0(const float* __restrict__ Z, const float* __restrict__ P,
                      float* __restrict__ H) {
    int q = blockIdx.x * blockDim.x + threadIdx.x;
    int cb = (q & 63) << 2;
    float4 z = reinterpret_cast<const float4*>(Z)[q];
    float4 p = reinterpret_cast<const float4*>(P)[q];
    float4 r;
    r.x = fmaf(g_affine[cb + 0], z.x, g_affine[256 + cb + 0]) + fmaf(g_affine[512 + cb + 0], p.x, g_affine[768 + cb + 0]);
    r.y = fmaf(g_affine[cb + 1], z.y, g_affine[256 + cb + 1]) + fmaf(g_affine[512 + cb + 1], p.y, g_affine[768 + cb + 1]);
    r.z = fmaf(g_affine[cb + 2], z.z, g_affine[256 + cb + 2]) + fmaf(g_affine[512 + cb + 2], p.z, g_affine[768 + cb + 2]);
    r.w = fmaf(g_affine[cb + 3], z.w, g_affine[256 + cb + 3]) + fmaf(g_affine[512 + cb + 3], p.w, g_affine[768 + cb + 3]);
    r.x = fmaxf(r.x, 0.f); r.y = fmaxf(r.y, 0.f); r.z = fmaxf(r.z, 0.f); r.w = fmaxf(r.w, 0.f);
    reinterpret_cast<float4*>(H)[q] = r;
}

__global__ void k_bn1(const float* __restrict__ Z, float* __restrict__ H) {
    int q = blockIdx.x * blockDim.x + threadIdx.x;
    int cb = (q & 63) << 2;
    float4 z = reinterpret_cast<const float4*>(Z)[q];
    float4 r;
    r.x = fmaf(g_affine[cb + 0], z.x, g_affine[256 + cb + 0]);
    r.y = fmaf(g_affine[cb + 1], z.y, g_affine[256 + cb + 1]);
    r.z = fmaf(g_affine[cb + 2], z.z, g_affine[256 + cb + 2]);
    r.w = fmaf(g_affine[cb + 3], z.w, g_affine[256 + cb + 3]);
    r.x = fmaxf(r.x, 0.f); r.y = fmaxf(r.y, 0.f); r.z = fmaxf(r.z, 0.f); r.w = fmaxf(r.w, 0.f);
    reinterpret_cast<float4*>(H)[q] = r;
}

// ---------------- launch ----------------
extern "C" void kernel_launch(void* const* d_in, const int* in_sizes, int n_in,
                              void* d_out, int out_size) {
    const float* LLM = (const float*)d_in[0];
    const float* PLM = (const float*)d_in[1];
    const int* src   = (const int*)d_in[2];
    const int* dst   = (const int*)d_in[3];
    const float* ws0 = (const float*)d_in[4];
    const float* wn0 = (const float*)d_in[5];
    const float* b0  = (const float*)d_in[6];
    const float* ws1 = (const float*)d_in[7];
    const float* wn1 = (const float*)d_in[8];
    const float* b1  = (const float*)d_in[9];
    const float* ws2 = (const float*)d_in[10];
    const float* wn2 = (const float*)d_in[11];
    const float* b2  = (const float*)d_in[12];
    const float* bn0w = (const float*)d_in[13];
    const float* bn0b = (const float*)d_in[14];
    const float* bn1w = (const float*)d_in[15];
    const float* bn1b = (const float*)d_in[16];
    float* out = (float*)d_out;

    float *pGs, *pGn, *pZ, *pH, *pAff;
    cudaGetSymbolAddress((void**)&pGs, g_Gs);
    cudaGetSymbolAddress((void**)&pGn, g_Gn);
    cudaGetSymbolAddress((void**)&pZ, g_Z);
    cudaGetSymbolAddress((void**)&pH, g_H);
    cudaGetSymbolAddress((void**)&pAff, g_affine);

    const int elem_blocks = (NN * DD / 4) / 256;  // 12500, exact
    dim3 ggemm(4, (NN + 127) / 128);
    dim3 ggemm2(1, (NN + 127) / 128);

    // launches 0-3: CSR build
    k_zero<<<(NN / 4 + 255) / 256, 256>>>();
    k_hist<<<(EE + 255) / 256, 256>>>(dst);
    k_scan<<<1, 1024>>>();
    k_scatter<<<(EE + 255) / 256, 256>>>(src, dst);

    // layer 0: gemm = launch 4, agg = launch 5 (ncu -s 5 window lands here)
    k_gemm_tf32<<<ggemm, 256>>>(LLM, NN, ws0, wn0, pGs, pGn);
    k_agg4<<<NN / 4, 256>>>(pGs, pGn, b0, pZ);
    k_colstats<<<STATS_BLOCKS, 256>>>(pZ);
    k_affine<<<1, 256>>>(bn0w, bn0b, pAff);
    k_colstats<<<STATS_BLOCKS, 256>>>(PLM);
    k_affine<<<1, 256>>>(bn0w, bn0b, pAff + 512);
    k_bn0<<<elem_blocks, 256>>>(pZ, PLM, pH);

    // layer 1
    k_gemm_tf32<<<ggemm, 256>>>(pH, NN, ws1, wn1, pGs, pGn);
    k_agg4<<<NN / 4, 256>>>(pGs, pGn, b1, pZ);
    k_colstats<<<STATS_BLOCKS, 256>>>(pZ);
    k_affine<<<1, 256>>>(bn1w, bn1b, pAff);
    k_bn1<<<elem_blocks, 256>>>(pZ, pH);

    // layer 2 (output)
    k_gemm_small<<<ggemm2, 256>>>(pH, NN, ws2, wn2, pGs, pGn);
    k_agg_small<<<NN, 64>>>(pGs, pGn, b2, out);

    (void)in_sizes; (void)n_in; (void)out_size;
}

// round 6
// speedup vs baseline: 1.7297x; 1.3881x over previous
#include <cuda_runtime.h>
#include <cstdint>

// Problem constants (fixed shapes)
#define NN 50000
#define EE 800000
#define DD 256
#define KK 256
#define NCLS 40
#define STATS_BLOCKS 400
#define BN_EPS 1e-5f

// ---------------- scratch (static device globals; no allocation) ----------------
__device__ __align__(16) float g_Gs[NN * DD];   // GEMM self output [N,256]
__device__ __align__(16) float g_Gn[NN * DD];   // GEMM neigh output [N,256] (dense gather target)
__device__ __align__(16) float g_Z[NN * DD];    // pre-BN activations
__device__ float g_part[STATS_BLOCKS * 512];    // per-block column sums / sumsq
__device__ float g_affine[1024];                // [0:256)=A_z,[256:512)=B_z,[512:768)=A_plm,[768:1024)=B_plm
__device__ float g_invdeg[NN];
__device__ __align__(16) int g_deg[NN];
__device__ __align__(16) int g_fill[NN];
__device__ int g_rowptr[NN + 1];
__device__ int g_csr[EE];

// ---------------- zero deg/fill ----------------
__global__ void k_zero() {
    int q = blockIdx.x * blockDim.x + threadIdx.x;  // int4 index, NN/4 = 12500
    if (q < NN / 4) {
        int4 z = make_int4(0, 0, 0, 0);
        reinterpret_cast<int4*>(g_deg)[q] = z;
        reinterpret_cast<int4*>(g_fill)[q] = z;
    }
}

// ---------------- CSR build ----------------
__global__ void k_hist(const int* __restrict__ dst) {
    int e = blockIdx.x * blockDim.x + threadIdx.x;
    if (e < EE) atomicAdd(&g_deg[dst[e]], 1);
}

// single-block exclusive scan of g_deg -> g_rowptr; also writes invdeg
__global__ void k_scan() {
    const int n = NN;
    const int CH = (n + 1023) / 1024;  // 49
    __shared__ int wsum[32];
    int t = threadIdx.x, lane = t & 31, w = t >> 5;
    int c0 = t * CH;
    int local = 0;
    for (int i = 0; i < CH; i++) {
        int idx = c0 + i;
        if (idx < n) local += g_deg[idx];
    }
    int v = local;
#pragma unroll
    for (int o = 1; o < 32; o <<= 1) {
        int u = __shfl_up_sync(0xffffffffu, v, o);
        if (lane >= o) v += u;
    }
    if (lane == 31) wsum[w] = v;
    __syncthreads();
    if (w == 0) {
        int x = wsum[lane];
#pragma unroll
        for (int o = 1; o < 32; o <<= 1) {
            int u = __shfl_up_sync(0xffffffffu, x, o);
            if (lane >= o) x += u;
        }
        wsum[lane] = x;
    }
    __syncthreads();
    int excl = (v - local) + (w > 0 ? wsum[w - 1] : 0);
    int run = excl;
    for (int i = 0; i < CH; i++) {
        int idx = c0 + i;
        if (idx < n) {
            int d = g_deg[idx];
            g_rowptr[idx] = run;
            run += d;
            g_invdeg[idx] = 1.0f / fmaxf((float)d, 1.0f);
        }
    }
    if (t == 1023) g_rowptr[n] = wsum[31];
}

__global__ void k_scatter(const int* __restrict__ src, const int* __restrict__ dst) {
    int e = blockIdx.x * blockDim.x + threadIdx.x;
    if (e < EE) {
        int d = dst[e];
        int pos = g_rowptr[d] + atomicAdd(&g_fill[d], 1);
        g_csr[pos] = src[e];
    }
}

// ================= BF16 tensor-core GEMM (3xBF16 hi/lo split) =================
// C[N,512] = act(A)[N,256] @ [Bself;Bneigh]^T, split outputs Cs/Cn.
// MODE 0: act = identity (A = raw input)
// MODE 1: act = relu(Az*A + Bz + Ap*P + Bp)   (bn0 + residual bn0(PLM) + relu)
// MODE 2: act = relu(Az*A + Bz)               (bn1 + relu)

__device__ __forceinline__ uint32_t pack_bf16x2(float lo_elem, float hi_elem) {
    // result.lo = bf16(lo_elem) (element k), result.hi = bf16(hi_elem) (element k+1)
    uint32_t r;
    asm("cvt.rn.bf16x2.f32 %0, %1, %2;" : "=r"(r) : "f"(hi_elem), "f"(lo_elem));
    return r;
}

__device__ __forceinline__ void split_pair(float v0, float v1, uint32_t& hi, uint32_t& lo) {
    uint32_t h = pack_bf16x2(v0, v1);
    float h0 = __uint_as_float(h << 16);
    float h1 = __uint_as_float(h & 0xffff0000u);
    lo = pack_bf16x2(v0 - h0, v1 - h1);
    hi = h;
}

__device__ __forceinline__ void mma_bf16(float* d, const uint32_t* a, const uint32_t* b) {
    asm volatile(
        "mma.sync.aligned.m16n8k16.row.col.f32.bf16.bf16.f32 "
        "{%0,%1,%2,%3}, {%4,%5,%6,%7}, {%8,%9}, {%0,%1,%2,%3};"
        : "+f"(d[0]), "+f"(d[1]), "+f"(d[2]), "+f"(d[3])
        : "r"(a[0]), "r"(a[1]), "r"(a[2]), "r"(a[3]), "r"(b[0]), "r"(b[1]));
}

#define WPAD 12  // smem word stride (8 kpairs + 4) -> conflict-free fragment loads

template <int MODE>
__global__ void __launch_bounds__(256) k_gemm_bf16(
    const float* __restrict__ A, const float* __restrict__ P,
    const float* __restrict__ aff, int N,
    const float* __restrict__ Bself, const float* __restrict__ Bneigh,
    float* __restrict__ Cs, float* __restrict__ Cn) {
    __shared__ uint32_t As_hi[128][WPAD];
    __shared__ uint32_t As_lo[128][WPAD];
    __shared__ uint32_t Bs_hi[128][WPAD];
    __shared__ uint32_t Bs_lo[128][WPAD];

    const int tid = threadIdx.x;
    const int lane = tid & 31;
    const int wid = tid >> 5;
    const int wm = (wid >> 2) * 64;
    const int wn = (wid & 3) * 32;
    const int g = lane >> 2;
    const int t = lane & 3;
    const int bm = blockIdx.y * 128;
    const int bn = blockIdx.x * 128;

    const int lr0 = tid >> 2;                 // 0..63
    const int lr1 = (tid + 256) >> 2;         // 64..127
    const int lc0 = (tid & 3) * 4;            // float col group
    const int wo = (tid & 3) * 2;             // word (kpair) offset
    const bool aok0 = (bm + lr0) < N;
    const bool aok1 = (bm + lr1) < N;
    const float* bp0 = (bn + lr0) < 256 ? (Bself + (bn + lr0) * KK) : (Bneigh + (bn + lr0 - 256) * KK);
    const float* bp1 = (bn + lr1) < 256 ? (Bself + (bn + lr1) * KK) : (Bneigh + (bn + lr1 - 256) * KK);

    float acc[4][4][4];
#pragma unroll
    for (int i = 0; i < 4; i++)
#pragma unroll
        for (int j = 0; j < 4; j++)
#pragma unroll
            for (int r = 0; r < 4; r++) acc[i][j][r] = 0.0f;

    const float4 z4 = make_float4(0.f, 0.f, 0.f, 0.f);
    float4 pa0, pa1, pb0, pb1, pp0, pp1;

    pa0 = aok0 ? *reinterpret_cast<const float4*>(A + (bm + lr0) * KK + lc0) : z4;
    pa1 = aok1 ? *reinterpret_cast<const float4*>(A + (bm + lr1) * KK + lc0) : z4;
    pb0 = *reinterpret_cast<const float4*>(bp0 + lc0);
    pb1 = *reinterpret_cast<const float4*>(bp1 + lc0);
    if (MODE == 1) {
        pp0 = aok0 ? *reinterpret_cast<const float4*>(P + (bm + lr0) * KK + lc0) : z4;
        pp1 = aok1 ? *reinterpret_cast<const float4*>(P + (bm + lr1) * KK + lc0) : z4;
    }

    for (int kc = 0; kc < KK / 16; kc++) {
        // --- activation on current A chunk ---
        float4 ea0 = pa0, ea1 = pa1;
        if (MODE != 0) {
            int cb = kc * 16 + lc0;
            float4 az = *reinterpret_cast<const float4*>(aff + cb);
            float4 bz = *reinterpret_cast<const float4*>(aff + 256 + cb);
            ea0.x = fmaf(az.x, pa0.x, bz.x); ea0.y = fmaf(az.y, pa0.y, bz.y);
            ea0.z = fmaf(az.z, pa0.z, bz.z); ea0.w = fmaf(az.w, pa0.w, bz.w);
            ea1.x = fmaf(az.x, pa1.x, bz.x); ea1.y = fmaf(az.y, pa1.y, bz.y);
            ea1.z = fmaf(az.z, pa1.z, bz.z); ea1.w = fmaf(az.w, pa1.w, bz.w);
            if (MODE == 1) {
                float4 ap = *reinterpret_cast<const float4*>(aff + 512 + cb);
                float4 bp = *reinterpret_cast<const float4*>(aff + 768 + cb);
                ea0.x += fmaf(ap.x, pp0.x, bp.x); ea0.y += fmaf(ap.y, pp0.y, bp.y);
                ea0.z += fmaf(ap.z, pp0.z, bp.z); ea0.w += fmaf(ap.w, pp0.w, bp.w);
                ea1.x += fmaf(ap.x, pp1.x, bp.x); ea1.y += fmaf(ap.y, pp1.y, bp.y);
                ea1.z += fmaf(ap.z, pp1.z, bp.z); ea1.w += fmaf(ap.w, pp1.w, bp.w);
            }
            ea0.x = fmaxf(ea0.x, 0.f); ea0.y = fmaxf(ea0.y, 0.f);
            ea0.z = fmaxf(ea0.z, 0.f); ea0.w = fmaxf(ea0.w, 0.f);
            ea1.x = fmaxf(ea1.x, 0.f); ea1.y = fmaxf(ea1.y, 0.f);
            ea1.z = fmaxf(ea1.z, 0.f); ea1.w = fmaxf(ea1.w, 0.f);
        }

        // --- convert + store to smem ---
        {
            uint32_t h, l;
            split_pair(ea0.x, ea0.y, h, l); As_hi[lr0][wo] = h; As_lo[lr0][wo] = l;
            split_pair(ea0.z, ea0.w, h, l); As_hi[lr0][wo + 1] = h; As_lo[lr0][wo + 1] = l;
            split_pair(ea1.x, ea1.y, h, l); As_hi[lr1][wo] = h; As_lo[lr1][wo] = l;
            split_pair(ea1.z, ea1.w, h, l); As_hi[lr1][wo + 1] = h; As_lo[lr1][wo + 1] = l;
            split_pair(pb0.x, pb0.y, h, l); Bs_hi[lr0][wo] = h; Bs_lo[lr0][wo] = l;
            split_pair(pb0.z, pb0.w, h, l); Bs_hi[lr0][wo + 1] = h; Bs_lo[lr0][wo + 1] = l;
            split_pair(pb1.x, pb1.y, h, l); Bs_hi[lr1][wo] = h; Bs_lo[lr1][wo] = l;
            split_pair(pb1.z, pb1.w, h, l); Bs_hi[lr1][wo + 1] = h; Bs_lo[lr1][wo + 1] = l;
        }
        __syncthreads();

        // --- prefetch next chunk ---
        if (kc + 1 < KK / 16) {
            int k0 = (kc + 1) * 16;
            pa0 = aok0 ? *reinterpret_cast<const float4*>(A + (bm + lr0) * KK + k0 + lc0) : z4;
            pa1 = aok1 ? *reinterpret_cast<const float4*>(A + (bm + lr1) * KK + k0 + lc0) : z4;
            pb0 = *reinterpret_cast<const float4*>(bp0 + k0 + lc0);
            pb1 = *reinterpret_cast<const float4*>(bp1 + k0 + lc0);
            if (MODE == 1) {
                pp0 = aok0 ? *reinterpret_cast<const float4*>(P + (bm + lr0) * KK + k0 + lc0) : z4;
                pp1 = aok1 ? *reinterpret_cast<const float4*>(P + (bm + lr1) * KK + k0 + lc0) : z4;
            }
        }

        // --- MMA: one m16n8k16 k-step per chunk ---
        {
            uint32_t ah[4][4], al[4][4], bh[4][2], bl[4][2];
#pragma unroll
            for (int mt = 0; mt < 4; mt++) {
                int m0 = wm + mt * 16;
                ah[mt][0] = As_hi[m0 + g][t];
                ah[mt][1] = As_hi[m0 + g + 8][t];
                ah[mt][2] = As_hi[m0 + g][t + 4];
                ah[mt][3] = As_hi[m0 + g + 8][t + 4];
                al[mt][0] = As_lo[m0 + g][t];
                al[mt][1] = As_lo[m0 + g + 8][t];
                al[mt][2] = As_lo[m0 + g][t + 4];
                al[mt][3] = As_lo[m0 + g + 8][t + 4];
            }
#pragma unroll
            for (int nt = 0; nt < 4; nt++) {
                int n0 = wn + nt * 8;
                bh[nt][0] = Bs_hi[n0 + g][t];
                bh[nt][1] = Bs_hi[n0 + g][t + 4];
                bl[nt][0] = Bs_lo[n0 + g][t];
                bl[nt][1] = Bs_lo[n0 + g][t + 4];
            }
#pragma unroll
            for (int mt = 0; mt < 4; mt++)
#pragma unroll
                for (int nt = 0; nt < 4; nt++) {
                    mma_bf16(acc[mt][nt], ah[mt], bh[nt]);  // hi*hi
                    mma_bf16(acc[mt][nt], ah[mt], bl[nt]);  // hi*lo
                    mma_bf16(acc[mt][nt], al[mt], bh[nt]);  // lo*hi
                }
        }
        __syncthreads();
    }

    float* Cbase = (bn < 256) ? (Cs + bn) : (Cn + (bn - 256));
#pragma unroll
    for (int mt = 0; mt < 4; mt++) {
#pragma unroll
        for (int nt = 0; nt < 4; nt++) {
            int row = bm + wm + mt * 16 + g;
            int col = wn + nt * 8 + 2 * t;
            if (row < N)
                *reinterpret_cast<float2*>(Cbase + row * 256 + col) =
                    make_float2(acc[mt][nt][0], acc[mt][nt][1]);
            if (row + 8 < N)
                *reinterpret_cast<float2*>(Cbase + (row + 8) * 256 + col) =
                    make_float2(acc[mt][nt][2], acc[mt][nt][3]);
        }
    }
}

// ---------------- SIMT GEMM for layer 2 (Mtot=80), fused bn1+relu on A ----------------
__global__ void __launch_bounds__(256) k_gemm_small(
    const float* __restrict__ A, const float* __restrict__ aff, int N,
    const float* __restrict__ Bself, const float* __restrict__ Bneigh,
    float* __restrict__ Cs, float* __restrict__ Cn) {
    __shared__ __align__(16) float As[16][132];
    __shared__ __align__(16) float Bs[16][132];
    const int Mtot = 2 * NCLS;  // 80
    const int bm = blockIdx.y * 128;
    const int tid = threadIdx.x;
    const int tr = (tid >> 4) << 3;
    const int tc = (tid & 15) << 3;

    float acc[8][8];
#pragma unroll
    for (int i = 0; i < 8; i++)
#pragma unroll
        for (int j = 0; j < 8; j++) acc[i][j] = 0.0f;

    for (int k0 = 0; k0 < KK; k0 += 16) {
#pragma unroll
        for (int i = 0; i < 2; i++) {
            int l = tid + i * 256;
            int r = l >> 2;
            int cg = (l & 3) << 2;
            int ar = bm + r;
            float4 av = make_float4(0.f, 0.f, 0.f, 0.f);
            if (ar < N) {
                float4 z = *reinterpret_cast<const float4*>(A + ar * KK + k0 + cg);
                float4 az = *reinterpret_cast<const float4*>(aff + k0 + cg);
                float4 bz = *reinterpret_cast<const float4*>(aff + 256 + k0 + cg);
                av.x = fmaxf(fmaf(az.x, z.x, bz.x), 0.f);
                av.y = fmaxf(fmaf(az.y, z.y, bz.y), 0.f);
                av.z = fmaxf(fmaf(az.z, z.z, bz.z), 0.f);
                av.w = fmaxf(fmaf(az.w, z.w, bz.w), 0.f);
            }
            As[cg + 0][r] = av.x; As[cg + 1][r] = av.y;
            As[cg + 2][r] = av.z; As[cg + 3][r] = av.w;

            float4 bv = make_float4(0.f, 0.f, 0.f, 0.f);
            if (r < Mtot) {
                const float* bp = (r < NCLS) ? (Bself + r * KK) : (Bneigh + (r - NCLS) * KK);
                bv = *reinterpret_cast<const float4*>(bp + k0 + cg);
            }
            Bs[cg + 0][r] = bv.x; Bs[cg + 1][r] = bv.y;
            Bs[cg + 2][r] = bv.z; Bs[cg + 3][r] = bv.w;
        }
        __syncthreads();
#pragma unroll
        for (int k = 0; k < 16; k++) {
            float4 a0 = *reinterpret_cast<const float4*>(&As[k][tr]);
            float4 a1 = *reinterpret_cast<const float4*>(&As[k][tr + 4]);
            float4 b0 = *reinterpret_cast<const float4*>(&Bs[k][tc]);
            float4 b1 = *reinterpret_cast<const float4*>(&Bs[k][tc + 4]);
            float av[8] = {a0.x, a0.y, a0.z, a0.w, a1.x, a1.y, a1.z, a1.w};
            float bv[8] = {b0.x, b0.y, b0.z, b0.w, b1.x, b1.y, b1.z, b1.w};
#pragma unroll
            for (int i = 0; i < 8; i++)
#pragma unroll
                for (int j = 0; j < 8; j++)
                    acc[i][j] = fmaf(av[i], bv[j], acc[i][j]);
        }
        __syncthreads();
    }

#pragma unroll
    for (int i = 0; i < 8; i++) {
        int r = bm + tr + i;
        if (r < N) {
#pragma unroll
            for (int j = 0; j < 8; j++) {
                int col = tc + j;
                if (col < NCLS) Cs[r * NCLS + col] = acc[i][j];
                else if (col < Mtot) Cn[r * NCLS + (col - NCLS)] = acc[i][j];
            }
        }
    }
}

// ---------------- Aggregation (float4, 4 nodes per block) ----------------
__global__ void __launch_bounds__(256) k_agg4(
    const float* __restrict__ Gs, const float* __restrict__ Gn,
    const float* __restrict__ bias, float* __restrict__ Z) {
    int sub = threadIdx.x >> 6;
    int cg = (threadIdx.x & 63) << 2;
    int i = blockIdx.x * 4 + sub;
    int e0 = g_rowptr[i];
    int e1 = g_rowptr[i + 1];
    float4 acc = make_float4(0.f, 0.f, 0.f, 0.f);
    int e = e0;
    for (; e + 4 <= e1; e += 4) {
        int s0 = g_csr[e + 0];
        int s1 = g_csr[e + 1];
        int s2 = g_csr[e + 2];
        int s3 = g_csr[e + 3];
        float4 v0 = __ldg(reinterpret_cast<const float4*>(Gn + s0 * DD + cg));
        float4 v1 = __ldg(reinterpret_cast<const float4*>(Gn + s1 * DD + cg));
        float4 v2 = __ldg(reinterpret_cast<const float4*>(Gn + s2 * DD + cg));
        float4 v3 = __ldg(reinterpret_cast<const float4*>(Gn + s3 * DD + cg));
        acc.x += (v0.x + v1.x) + (v2.x + v3.x);
        acc.y += (v0.y + v1.y) + (v2.y + v3.y);
        acc.z += (v0.z + v1.z) + (v2.z + v3.z);
        acc.w += (v0.w + v1.w) + (v2.w + v3.w);
    }
    for (; e < e1; e++) {
        float4 v = __ldg(reinterpret_cast<const float4*>(Gn + g_csr[e] * DD + cg));
        acc.x += v.x; acc.y += v.y; acc.z += v.z; acc.w += v.w;
    }
    float inv = g_invdeg[i];
    float4 self = *reinterpret_cast<const float4*>(Gs + i * DD + cg);
    float4 b = *reinterpret_cast<const float4*>(bias + cg);
    float4 r;
    r.x = fmaf(inv, acc.x, self.x) + b.x;
    r.y = fmaf(inv, acc.y, self.y) + b.y;
    r.z = fmaf(inv, acc.z, self.z) + b.z;
    r.w = fmaf(inv, acc.w, self.w) + b.w;
    *reinterpret_cast<float4*>(Z + i * DD + cg) = r;
}

// scalar agg for layer 2 (D = NCLS = 40)
__global__ void k_agg_small(const float* __restrict__ Gs, const float* __restrict__ Gn,
                            const float* __restrict__ bias, float* __restrict__ Z) {
    int i = blockIdx.x;
    int c = threadIdx.x;
    if (c >= NCLS) return;
    int e0 = g_rowptr[i];
    int e1 = g_rowptr[i + 1];
    float accn = 0.0f;
    int e = e0;
    for (; e + 4 <= e1; e += 4) {
        int s0 = g_csr[e + 0];
        int s1 = g_csr[e + 1];
        int s2 = g_csr[e + 2];
        int s3 = g_csr[e + 3];
        float v0 = __ldg(Gn + s0 * NCLS + c);
        float v1 = __ldg(Gn + s1 * NCLS + c);
        float v2 = __ldg(Gn + s2 * NCLS + c);
        float v3 = __ldg(Gn + s3 * NCLS + c);
        accn += (v0 + v1) + (v2 + v3);
    }
    for (; e < e1; e++) accn += __ldg(Gn + g_csr[e] * NCLS + c);
    Z[i * NCLS + c] = fmaf(g_invdeg[i], accn, Gs[i * NCLS + c]) + bias[c];
}

// ---------------- column stats (deterministic 2-stage) ----------------
__global__ void k_colstats(const float* __restrict__ X) {
    int c = threadIdx.x;
    int rows_per = (NN + gridDim.x - 1) / gridDim.x;
    int r0 = blockIdx.x * rows_per;
    int r1 = min(NN, r0 + rows_per);
    float s = 0.f, s2 = 0.f;
#pragma unroll 4
    for (int r = r0; r < r1; r++) {
        float v = X[r * DD + c];
        s += v;
        s2 = fmaf(v, v, s2);
    }
    g_part[blockIdx.x * 512 + c] = s;
    g_part[blockIdx.x * 512 + 256 + c] = s2;
}

__global__ void k_affine(const float* __restrict__ gamma, const float* __restrict__ beta,
                         float* __restrict__ AB) {
    int c = threadIdx.x;
    float s = 0.f, s2 = 0.f;
    for (int b = 0; b < STATS_BLOCKS; b++) {
        s += g_part[b * 512 + c];
        s2 += g_part[b * 512 + 256 + c];
    }
    float m = s / (float)NN;
    float var = s2 / (float)NN - m * m;
    float a = gamma[c] * rsqrtf(var + BN_EPS);
    AB[c] = a;
    AB[256 + c] = beta[c] - m * a;
}

// ---------------- launch ----------------
extern "C" void kernel_launch(void* const* d_in, const int* in_sizes, int n_in,
                              void* d_out, int out_size) {
    const float* LLM = (const float*)d_in[0];
    const float* PLM = (const float*)d_in[1];
    const int* src   = (const int*)d_in[2];
    const int* dst   = (const int*)d_in[3];
    const float* ws0 = (const float*)d_in[4];
    const float* wn0 = (const float*)d_in[5];
    const float* b0  = (const float*)d_in[6];
    const float* ws1 = (const float*)d_in[7];
    const float* wn1 = (const float*)d_in[8];
    const float* b1  = (const float*)d_in[9];
    const float* ws2 = (const float*)d_in[10];
    const float* wn2 = (const float*)d_in[11];
    const float* b2  = (const float*)d_in[12];
    const float* bn0w = (const float*)d_in[13];
    const float* bn0b = (const float*)d_in[14];
    const float* bn1w = (const float*)d_in[15];
    const float* bn1b = (const float*)d_in[16];
    float* out = (float*)d_out;

    float *pGs, *pGn, *pZ, *pAff;
    cudaGetSymbolAddress((void**)&pGs, g_Gs);
    cudaGetSymbolAddress((void**)&pGn, g_Gn);
    cudaGetSymbolAddress((void**)&pZ, g_Z);
    cudaGetSymbolAddress((void**)&pAff, g_affine);

    dim3 ggemm(4, (NN + 127) / 128);
    dim3 ggemm2(1, (NN + 127) / 128);

    // CSR build
    k_zero<<<(NN / 4 + 255) / 256, 256>>>();
    k_hist<<<(EE + 255) / 256, 256>>>(dst);
    k_scan<<<1, 1024>>>();
    k_scatter<<<(EE + 255) / 256, 256>>>(src, dst);

    // layer 0: plain GEMM on LLM, aggregate -> Z0
    k_gemm_bf16<0><<<ggemm, 256>>>(LLM, nullptr, nullptr, NN, ws0, wn0, pGs, pGn);
    k_agg4<<<NN / 4, 256>>>(pGs, pGn, b0, pZ);

    // bn0 affines for Z0 and PLM
    k_colstats<<<STATS_BLOCKS, 256>>>(pZ);
    k_affine<<<1, 256>>>(bn0w, bn0b, pAff);
    k_colstats<<<STATS_BLOCKS, 256>>>(PLM);
    k_affine<<<1, 256>>>(bn0w, bn0b, pAff + 512);

    // layer 1: GEMM with fused bn0+residual+relu on A-load, aggregate -> Z1 (reuse pZ)
    k_gemm_bf16<1><<<ggemm, 256>>>(pZ, PLM, pAff, NN, ws1, wn1, pGs, pGn);
    k_agg4<<<NN / 4, 256>>>(pGs, pGn, b1, pZ);

    // bn1 affine for Z1
    k_colstats<<<STATS_BLOCKS, 256>>>(pZ);
    k_affine<<<1, 256>>>(bn1w, bn1b, pAff);

    // layer 2: SIMT GEMM with fused bn1+relu, aggregate -> out
    k_gemm_small<<<ggemm2, 256>>>(pZ, pAff, NN, ws2, wn2, pGs, pGn);
    k_agg_small<<<NN, 64>>>(pGs, pGn, b2, out);

    (void)in_sizes; (void)n_in; (void)out_size;
}